// round 5
// baseline (speedup 1.0000x reference)
#include <cuda_runtime.h>

// iBlockRaw: bn=32, pn=64, pl=128, N_HEAD=4, QK=4, VD=4, NVAR=1
// B = 2048 sequences of length 128. One CTA per sequence, one thread per query.
//
// Algebraic structure exploited (NVAR==1 => token embedding is a scalar):
//  1. v_h(m) = x_m * wv_h  =>  o_h(l) = wv_h * s_h(l)  with scalar s_h(l).
//  2. RoPE relative-phase: q_h(l)·k_h(m) = x_l x_m * sum_p [C_hp cos(dt th_p) - D_hp sin(dt th_p)]
//     => score_h(l,m) = dot4( AB_h(l), x_m*(cos tm, sin tm, cos th1 tm, sin th1 tm) ),
//     AB_h(l) per-query with mask_l * x_l * (0.5*log2e) folded in.
//  3. FFN folded: out = beta + sum_h s_h*alpha_h + sum_j r_j*relu(b1_j + sum_h s_h*m1[j][h]).
//  4. Masked query rows (-1e9 finite => uniform softmax): AB=0 -> all scores 0 -> exp=1,
//     and per-key weights forced to (x_m, 1) via offset selection => exact uniform mean.
//     Unmasked queries always see >=1 unmasked key (themselves) => den > 0 always.
//  5. Inner loop fully packed f32x2 (FFMA2); key data stored duplicated in smem so
//     LDS.128 delivers 64-bit lane-pairs directly; all reads are warp-broadcast.

#define LOG2E  1.4426950408889634f
#define THETA1 0.03162277660168379f   // 1000^{-0.5}

typedef unsigned long long u64;

__device__ __forceinline__ float ex2(float x) {
    float r;
    asm("ex2.approx.ftz.f32 %0, %1;" : "=f"(r) : "f"(x));
    return r;
}
__device__ __forceinline__ u64 pk2(float lo, float hi) {
    u64 r;
    asm("mov.b64 %0, {%1, %2};" : "=l"(r) : "f"(lo), "f"(hi));
    return r;
}
__device__ __forceinline__ void upk2(float& lo, float& hi, u64 v) {
    asm("mov.b64 {%0, %1}, %2;" : "=f"(lo), "=f"(hi) : "l"(v));
}
__device__ __forceinline__ u64 fma2(u64 a, u64 b, u64 c) {
    u64 d;
    asm("fma.rn.f32x2 %0, %1, %2, %3;" : "=l"(d) : "l"(a), "l"(b), "l"(c));
    return d;
}
__device__ __forceinline__ u64 mul2(u64 a, u64 b) {
    u64 d;
    asm("mul.rn.f32x2 %0, %1, %2;" : "=l"(d) : "l"(a), "l"(b));
    return d;
}

__global__ __launch_bounds__(128) void attn_kernel(
    const float* __restrict__ x, const float* __restrict__ t,
    const int* __restrict__ mask,
    const float* __restrict__ Wq, const float* __restrict__ Wk,
    const float* __restrict__ Wv, const float* __restrict__ Wout,
    const float* __restrict__ W1, const float* __restrict__ b1,
    const float* __restrict__ W2, const float* __restrict__ b2,
    float* __restrict__ out) {
    // Per-key row (64B): [0..7] duplicated trig*x pairs, [8..11] (x*m, x*m, m, m),
    //                    [12..15] (x, x, 1, 1)
    __shared__ __align__(16) float sk[128][16];
    __shared__ __align__(16) float sffn[392]; // [0..255] m1 (float4 per j), [256..383] (b1_j, r_j),
                                              // [384..387] alpha, [388] beta
    __shared__ __align__(16) float sCD[16];   // per head: C0, D0, C1, D1

    const int l = threadIdx.x;
    const int base = blockIdx.x * 128;

    const float xv = x[base + l];
    const float tv = t[base + l];
    const int   mi = mask[base + l];
    const float mlf = (float)mi;

    float s0, c0, s1, c1;
    __sincosf(tv, &s0, &c0);
    __sincosf(tv * THETA1, &s1, &c1);

    // ---- stage per-key data (duplicated for f32x2 lanes) ----
    ((float4*)sk[l])[0] = make_float4(xv * c0, xv * c0, xv * s0, xv * s0);
    ((float4*)sk[l])[1] = make_float4(xv * c1, xv * c1, xv * s1, xv * s1);
    ((float4*)sk[l])[2] = make_float4(xv * mlf, xv * mlf, mlf, mlf);
    ((float4*)sk[l])[3] = make_float4(xv, xv, 1.0f, 1.0f);

    // ---- fold weights per-CTA (weights are tiny; L2-resident after first wave) ----
    if (l < 64) {
        const int j = l;
        #pragma unroll
        for (int h = 0; h < 4; h++) {
            float acc = 0.f;
            #pragma unroll
            for (int d = 0; d < 4; d++)
                acc += W1[j * 16 + 4 * h + d] * Wv[4 * h + d];
            sffn[4 * j + h] = acc;                 // m1[j][h]
        }
        float r = 0.f;
        #pragma unroll
        for (int i = 0; i < 16; i++) r += Wout[i] * W2[i * 64 + j];
        sffn[256 + 2 * j]     = b1[j];             // (b1_j, r_j) pair
        sffn[256 + 2 * j + 1] = r;
    }
    if (l < 4) {
        const int h = l;
        float a = 0.f;
        #pragma unroll
        for (int d = 0; d < 4; d++) a += Wout[4 * h + d] * Wv[4 * h + d];
        sffn[384 + h] = a;                         // alpha_h
        #pragma unroll
        for (int p = 0; p < 2; p++) {
            float ar = Wq[4 * h + 2 * p], ai = Wq[4 * h + 2 * p + 1];
            float br = Wk[4 * h + 2 * p], bi = Wk[4 * h + 2 * p + 1];
            sCD[4 * h + 2 * p + 0] = ar * br + ai * bi;  // C
            sCD[4 * h + 2 * p + 1] = ar * bi - ai * br;  // D = -E
        }
    }
    if (l == 4) {
        float bs = 0.f;
        #pragma unroll
        for (int i = 0; i < 16; i++) bs += Wout[i] * b2[i];
        sffn[388] = bs;                            // beta
    }
    __syncthreads();

    // ---- per-query packed score vectors: AB01[p] = (head0, head1), AB23[p] = (head2, head3)
    const float qsc = mlf * xv * (0.5f * LOG2E);
    float AB[16];
    #pragma unroll
    for (int h = 0; h < 4; h++) {
        const float C0 = sCD[4 * h + 0], D0 = sCD[4 * h + 1];
        const float C1 = sCD[4 * h + 2], D1 = sCD[4 * h + 3];
        AB[4 * h + 0] = qsc * (C0 * c0 + D0 * s0);
        AB[4 * h + 1] = qsc * (C0 * s0 - D0 * c0);
        AB[4 * h + 2] = qsc * (C1 * c1 + D1 * s1);
        AB[4 * h + 3] = qsc * (C1 * s1 - D1 * c1);
    }
    u64 AB01[4], AB23[4];
    #pragma unroll
    for (int p = 0; p < 4; p++) {
        AB01[p] = pk2(AB[p],     AB[4 + p]);
        AB23[p] = pk2(AB[8 + p], AB[12 + p]);
    }

    // weight-variant selection: masked query uses (x, 1); unmasked uses (x*m, m)
    const float* kw = &sk[0][mi ? 8 : 12];

    u64 num01 = 0ULL, num23 = 0ULL, den01 = 0ULL, den23 = 0ULL;

    #pragma unroll 4
    for (int m = 0; m < 128; m++) {
        const float* kr = sk[m];
        const ulonglong2 tA = *(const ulonglong2*)(kr);          // (xc2, xs2)
        const ulonglong2 tB = *(const ulonglong2*)(kr + 4);      // (xc12, xs12)
        const ulonglong2 tC = *(const ulonglong2*)(kw + m * 16); // (xw2, wv2)

        u64 sp01 = fma2(tA.x, AB01[0], fma2(tA.y, AB01[1],
                   fma2(tB.x, AB01[2], mul2(tB.y, AB01[3]))));
        u64 sp23 = fma2(tA.x, AB23[0], fma2(tA.y, AB23[1],
                   fma2(tB.x, AB23[2], mul2(tB.y, AB23[3]))));

        float sA, sB, sC, sD;
        upk2(sA, sB, sp01);
        upk2(sC, sD, sp23);
        const u64 e01 = pk2(ex2(sA), ex2(sB));
        const u64 e23 = pk2(ex2(sC), ex2(sD));

        num01 = fma2(e01, tC.x, num01);
        den01 = fma2(e01, tC.y, den01);
        num23 = fma2(e23, tC.x, num23);
        den23 = fma2(e23, tC.y, den23);
    }

    float n0, n1, n2, n3, d0, d1, d2, d3;
    upk2(n0, n1, num01); upk2(n2, n3, num23);
    upk2(d0, d1, den01); upk2(d2, d3, den23);
    const float sh0 = __fdividef(n0, d0);
    const float sh1 = __fdividef(n1, d1);
    const float sh2 = __fdividef(n2, d2);
    const float sh3 = __fdividef(n3, d3);

    // ---- folded FFN epilogue (packed) ----
    const u64 sh01 = pk2(sh0, sh1);
    const u64 sh23 = pk2(sh2, sh3);

    float acc = sffn[388];
    acc = fmaf(sh0, sffn[384], acc);
    acc = fmaf(sh1, sffn[385], acc);
    acc = fmaf(sh2, sffn[386], acc);
    acc = fmaf(sh3, sffn[387], acc);

    const ulonglong2* m1v = (const ulonglong2*)sffn;   // m1[j] as (h0,h1),(h2,h3)
    const float2*     b1r = (const float2*)(sffn + 256);
    #pragma unroll 8
    for (int j = 0; j < 64; j++) {
        const ulonglong2 mm = m1v[j];
        const float2 br = b1r[j];
        // (b1_j, 0) + sh01*(m0,m1) + sh23*(m2,m3), then horizontal add
        u64 hv = fma2(sh01, mm.x, fma2(sh23, mm.y, pk2(br.x, 0.f)));
        float hlo, hhi;
        upk2(hlo, hhi, hv);
        float h = fmaxf(hlo + hhi, 0.f);
        acc = fmaf(br.y, h, acc);              // r_j
    }

    out[base + l] = acc;
}

extern "C" void kernel_launch(void* const* d_in, const int* in_sizes, int n_in,
                              void* d_out, int out_size) {
    const float* x    = (const float*)d_in[0];
    const float* t    = (const float*)d_in[1];
    const int*   mask = (const int*)d_in[2];
    const float* Wq   = (const float*)d_in[3];
    const float* Wk   = (const float*)d_in[4];
    const float* Wv   = (const float*)d_in[5];
    const float* Wout = (const float*)d_in[6];
    const float* W1   = (const float*)d_in[7];
    const float* b1   = (const float*)d_in[8];
    const float* W2   = (const float*)d_in[9];
    const float* b2   = (const float*)d_in[10];
    float* out = (float*)d_out;

    const int ntok    = in_sizes[0];   // bn*pn*pl = 262144
    const int nblocks = ntok / 128;    // 2048 sequences

    attn_kernel<<<nblocks, 128>>>(x, t, mask, Wq, Wk, Wv, Wout, W1, b1, W2, b2, out);
}

// round 14
// speedup vs baseline: 1.4905x; 1.4905x over previous
#include <cuda_runtime.h>

// iBlockRaw: bn=32, pn=64, pl=128, N_HEAD=4, QK=4, VD=4, NVAR=1
// One CTA per sequence (2048 CTAs), one thread per query.
//
// R5 ncu baseline: 53.0us, L1 (LDS data-return) 74% binding at 48B/lane/iter.
// Frozen candidate (unchanged since R8; GPU unavailable R6-R13):
//  - 24B/lane/iter smem key rows (horizontal packed scores via fma2 + scalar FADD)
//  - stream-compaction of UNMASKED keys (masked keys carry zero weight for every
//    unmasked query) -> expected trip count ~64 instead of 128
//  - scalar (num,den) FFMA accumulation (weight==1 after compaction; padding rows
//    have x=0 AND w=0, so they are exact no-ops in both num and den)
//  - masked-query rows (uniform softmax over ALL keys) via block-reduced sum(x),
//    applied as an unconditional overwrite (degenerate num/den cannot propagate)

#define LOG2E  1.4426950408889634f
#define THETA1 0.03162277660168379f   // 1000^{-0.5}

typedef unsigned long long u64;

__device__ __forceinline__ float ex2(float x) {
    float r;
    asm("ex2.approx.ftz.f32 %0, %1;" : "=f"(r) : "f"(x));
    return r;
}
__device__ __forceinline__ u64 pk2(float lo, float hi) {
    u64 r;
    asm("mov.b64 %0, {%1, %2};" : "=l"(r) : "f"(lo), "f"(hi));
    return r;
}
__device__ __forceinline__ void upk2(float& lo, float& hi, u64 v) {
    asm("mov.b64 {%0, %1}, %2;" : "=f"(lo), "=f"(hi) : "l"(v));
}
__device__ __forceinline__ u64 fma2(u64 a, u64 b, u64 c) {
    u64 d;
    asm("fma.rn.f32x2 %0, %1, %2, %3;" : "=l"(d) : "l"(a), "l"(b), "l"(c));
    return d;
}
__device__ __forceinline__ u64 mul2(u64 a, u64 b) {
    u64 d;
    asm("mul.rn.f32x2 %0, %1, %2;" : "=l"(d) : "l"(a), "l"(b));
    return d;
}

__global__ __launch_bounds__(128) void attn_kernel(
    const float* __restrict__ x, const float* __restrict__ t,
    const int* __restrict__ mask,
    const float* __restrict__ Wq, const float* __restrict__ Wk,
    const float* __restrict__ Wv, const float* __restrict__ Wout,
    const float* __restrict__ W1, const float* __restrict__ b1,
    const float* __restrict__ W2, const float* __restrict__ b2,
    float* __restrict__ out) {
    // Compacted key row (32B): [0..3] (x*c0, x*s0, x*c1, x*s1), [4] x, [5] w(=1; pad 0)
    __shared__ __align__(16) float sk[128][8];
    __shared__ __align__(16) float sffn[392]; // [0..255] m1 (float4/j), [256..383] (b1_j, r_j),
                                              // [384..387] alpha, [388] beta
    __shared__ __align__(16) float sCD[16];   // per head: C0, D0, C1, D1
    __shared__ float sred[4];                 // warp partial sums of x
    __shared__ int   swcnt[4];                // per-warp unmasked-key counts

    const int l   = threadIdx.x;
    const int wid = l >> 5;
    const int lid = l & 31;
    const int base = blockIdx.x * 128;

    const float xv = x[base + l];
    const float tv = t[base + l];
    const int   mi = mask[base + l];
    const float mlf = (float)mi;

    float s0, c0, s1, c1;
    __sincosf(tv, &s0, &c0);
    __sincosf(tv * THETA1, &s1, &c1);

    // ---- compaction bookkeeping + block reduction of x ----
    const unsigned bal = __ballot_sync(0xffffffffu, mi != 0);
    {
        float sx = xv;
        #pragma unroll
        for (int off = 16; off > 0; off >>= 1)
            sx += __shfl_xor_sync(0xffffffffu, sx, off);
        if (lid == 0) {
            sred[wid]  = sx;
            swcnt[wid] = __popc(bal);
        }
    }

    // ---- fold weights per-CTA (tiny; L2-resident after first wave) ----
    if (l < 64) {
        const int j = l;
        #pragma unroll
        for (int h = 0; h < 4; h++) {
            float acc = 0.f;
            #pragma unroll
            for (int d = 0; d < 4; d++)
                acc += W1[j * 16 + 4 * h + d] * Wv[4 * h + d];
            sffn[4 * j + h] = acc;                 // m1[j][h]
        }
        float r = 0.f;
        #pragma unroll
        for (int i = 0; i < 16; i++) r += Wout[i] * W2[i * 64 + j];
        sffn[256 + 2 * j]     = b1[j];             // (b1_j, r_j) pair
        sffn[256 + 2 * j + 1] = r;
    }
    if (l < 4) {
        const int h = l;
        float a = 0.f;
        #pragma unroll
        for (int d = 0; d < 4; d++) a += Wout[4 * h + d] * Wv[4 * h + d];
        sffn[384 + h] = a;                         // alpha_h
        #pragma unroll
        for (int p = 0; p < 2; p++) {
            float ar = Wq[4 * h + 2 * p], ai = Wq[4 * h + 2 * p + 1];
            float br = Wk[4 * h + 2 * p], bi = Wk[4 * h + 2 * p + 1];
            sCD[4 * h + 2 * p + 0] = ar * br + ai * bi;  // C
            sCD[4 * h + 2 * p + 1] = ar * bi - ai * br;  // D = -E
        }
    }
    if (l == 4) {
        float bs = 0.f;
        #pragma unroll
        for (int i = 0; i < 16; i++) bs += Wout[i] * b2[i];
        sffn[388] = bs;                            // beta
    }
    __syncthreads();

    // ---- scatter compacted unmasked-key rows; pad to multiple of 8 with zero rows ----
    const int n = swcnt[0] + swcnt[1] + swcnt[2] + swcnt[3];
    const int npad = (n + 7) & ~7;
    int off = 0;
    #pragma unroll
    for (int w = 0; w < 4; w++)
        if (w < wid) off += swcnt[w];
    if (mi) {
        const int pos = off + __popc(bal & ((1u << lid) - 1u));
        ((float4*)sk[pos])[0] = make_float4(xv * c0, xv * s0, xv * c1, xv * s1);
        ((float2*)sk[pos])[2] = make_float2(xv, 1.0f);
    }
    if (l < npad - n) {
        const int pos = n + l;    // zero rows: score 0 -> e=1, but w=0 and x=0 kill it
        ((float4*)sk[pos])[0] = make_float4(0.f, 0.f, 0.f, 0.f);
        ((float2*)sk[pos])[2] = make_float2(0.f, 0.f);
    }

    // ---- per-query packed score vectors (reads sCD written before the barrier) ----
    const float qsc = mlf * xv * (0.5f * LOG2E);
    u64 AB01[4], AB23[4];
    #pragma unroll
    for (int h = 0; h < 4; h++) {
        const float C0 = sCD[4 * h + 0], D0 = sCD[4 * h + 1];
        const float C1 = sCD[4 * h + 2], D1 = sCD[4 * h + 3];
        AB01[h] = pk2(qsc * (C0 * c0 + D0 * s0), qsc * (C0 * s0 - D0 * c0));
        AB23[h] = pk2(qsc * (C1 * c1 + D1 * s1), qsc * (C1 * s1 - D1 * c1));
    }
    __syncthreads();

    float num0 = 0.f, num1 = 0.f, num2 = 0.f, num3 = 0.f;
    float den0 = 0.f, den1 = 0.f, den2 = 0.f, den3 = 0.f;

    #pragma unroll 4
    for (int m = 0; m < npad; m++) {
        const float* kr = sk[m];
        const ulonglong2 tA = *(const ulonglong2*)kr;   // (xc0,xs0), (xc1,xs1)
        const float2 xw = *(const float2*)(kr + 4);     // (x, w)

        const u64 t0 = fma2(tA.x, AB01[0], mul2(tA.y, AB23[0]));
        const u64 t1 = fma2(tA.x, AB01[1], mul2(tA.y, AB23[1]));
        const u64 t2 = fma2(tA.x, AB01[2], mul2(tA.y, AB23[2]));
        const u64 t3 = fma2(tA.x, AB01[3], mul2(tA.y, AB23[3]));

        float a0, b0, a1, b1_, a2, b2_, a3, b3;
        upk2(a0, b0, t0); upk2(a1, b1_, t1);
        upk2(a2, b2_, t2); upk2(a3, b3, t3);

        const float e0 = ex2(a0 + b0);
        const float e1 = ex2(a1 + b1_);
        const float e2 = ex2(a2 + b2_);
        const float e3 = ex2(a3 + b3);

        num0 = fmaf(e0, xw.x, num0); den0 = fmaf(e0, xw.y, den0);
        num1 = fmaf(e1, xw.x, num1); den1 = fmaf(e1, xw.y, den1);
        num2 = fmaf(e2, xw.x, num2); den2 = fmaf(e2, xw.y, den2);
        num3 = fmaf(e3, xw.x, num3); den3 = fmaf(e3, xw.y, den3);
    }

    float sh0 = __fdividef(num0, den0);
    float sh1 = __fdividef(num1, den1);
    float sh2 = __fdividef(num2, den2);
    float sh3 = __fdividef(num3, den3);

    // masked query: reference gives uniform softmax over ALL keys -> s_h = mean(x)
    if (mi == 0) {
        const float Sx = sred[0] + sred[1] + sred[2] + sred[3];
        const float shm = Sx * (1.0f / 128.0f);
        sh0 = shm; sh1 = shm; sh2 = shm; sh3 = shm;
    }

    // ---- folded FFN epilogue (packed) ----
    const u64 sh01 = pk2(sh0, sh1);
    const u64 sh23 = pk2(sh2, sh3);

    float acc = sffn[388];
    acc = fmaf(sh0, sffn[384], acc);
    acc = fmaf(sh1, sffn[385], acc);
    acc = fmaf(sh2, sffn[386], acc);
    acc = fmaf(sh3, sffn[387], acc);

    const ulonglong2* m1v = (const ulonglong2*)sffn;   // m1[j] as (h0,h1),(h2,h3)
    const float2*     b1r = (const float2*)(sffn + 256);
    #pragma unroll 8
    for (int j = 0; j < 64; j++) {
        const ulonglong2 mm = m1v[j];
        const float2 br = b1r[j];
        u64 hv = fma2(sh01, mm.x, fma2(sh23, mm.y, pk2(br.x, 0.f)));
        float hlo, hhi;
        upk2(hlo, hhi, hv);
        float h = fmaxf(hlo + hhi, 0.f);
        acc = fmaf(br.y, h, acc);              // r_j
    }

    out[base + l] = acc;
}

extern "C" void kernel_launch(void* const* d_in, const int* in_sizes, int n_in,
                              void* d_out, int out_size) {
    const float* x    = (const float*)d_in[0];
    const float* t    = (const float*)d_in[1];
    const int*   mask = (const int*)d_in[2];
    const float* Wq   = (const float*)d_in[3];
    const float* Wk   = (const float*)d_in[4];
    const float* Wv   = (const float*)d_in[5];
    const float* Wout = (const float*)d_in[6];
    const float* W1   = (const float*)d_in[7];
    const float* b1   = (const float*)d_in[8];
    const float* W2   = (const float*)d_in[9];
    const float* b2   = (const float*)d_in[10];
    float* out = (float*)d_out;

    const int ntok    = in_sizes[0];   // bn*pn*pl = 262144
    const int nblocks = ntok / 128;    // 2048 sequences

    attn_kernel<<<nblocks, 128>>>(x, t, mask, Wq, Wk, Wv, Wout, W1, b1, W2, b2, out);
}